// round 16
// baseline (speedup 1.0000x reference)
#include <cuda_runtime.h>
#include <cuda_fp16.h>
#include <cstdint>

#define MTOT   200704
#define NWIN   4096
#define HEADS  8
#define GWIN   5            // windows per group (packed 49 rows each; 245 of 256)
#define NGRP   820          // ceil(4096/5)
#define NPCTA  148          // 4 head-pairs x 37 persistent CTAs (1/SM, 512 thr)
#define CPH    37

// Scratch (device globals; no cudaMalloc allowed)
__device__ __half g_xh   [51380224];    // x converted to fp16
__device__ __half g_atth [51380224];    // [MTOT][256] fp16
__device__ __half g_wqkvTh[768 * 256];  // w_qkv^T [N][K] fp16
__device__ __half g_woutTh[256 * 256];  // w_out^T [N][K] fp16
__device__ float  g_biasmat[8 * 64 * 64]; // per-head bias matrix, masked

// ===========================================================================
// Helpers
// ===========================================================================
__device__ __forceinline__ uint32_t smem_u32(const void* p) {
    uint32_t a;
    asm("{ .reg .u64 t; cvta.to.shared.u64 t, %1; cvt.u32.u64 %0, t; }"
        : "=r"(a) : "l"(p));
    return a;
}

__device__ __forceinline__ uint32_t pack_half2(float a, float b) {
    __half2 h = __floats2half2_rn(a, b);
    return *(uint32_t*)&h;
}

__device__ __forceinline__ void mma16(float d[4],
                                      uint32_t a0, uint32_t a1, uint32_t a2, uint32_t a3,
                                      uint32_t b0, uint32_t b1) {
    asm volatile(
        "mma.sync.aligned.m16n8k16.row.col.f32.f16.f16.f32 "
        "{%0,%1,%2,%3}, {%4,%5,%6,%7}, {%8,%9}, {%0,%1,%2,%3};"
        : "+f"(d[0]), "+f"(d[1]), "+f"(d[2]), "+f"(d[3])
        : "r"(a0), "r"(a1), "r"(a2), "r"(a3), "r"(b0), "r"(b1));
}

__device__ __forceinline__ void ldsm_x4(uint32_t& d0, uint32_t& d1,
                                        uint32_t& d2, uint32_t& d3, uint32_t addr) {
    asm volatile("ldmatrix.sync.aligned.m8n8.x4.shared.b16 {%0,%1,%2,%3}, [%4];"
                 : "=r"(d0), "=r"(d1), "=r"(d2), "=r"(d3) : "r"(addr));
}

__device__ __forceinline__ void ldsm_x4t(uint32_t& d0, uint32_t& d1,
                                         uint32_t& d2, uint32_t& d3, uint32_t addr) {
    asm volatile("ldmatrix.sync.aligned.m8n8.x4.trans.shared.b16 {%0,%1,%2,%3}, [%4];"
                 : "=r"(d0), "=r"(d1), "=r"(d2), "=r"(d3) : "r"(addr));
}

#define CP16(dst_u32, src_ptr) \
    asm volatile("cp.async.ca.shared.global [%0], [%1], 16;" \
                 :: "r"(dst_u32), "l"(src_ptr))
#define CP16Z(dst_u32, src_ptr, nbytes) \
    asm volatile("cp.async.ca.shared.global [%0], [%1], 16, %2;" \
                 :: "r"(dst_u32), "l"(src_ptr), "r"(nbytes))
#define CP_COMMIT() asm volatile("cp.async.commit_group;")
#define CP_WAIT(n)  asm volatile("cp.async.wait_group %0;" :: "n"(n))

// Pixel-row offset in x for window `win`, token `t` (t < 49)
__device__ __forceinline__ int xrow_from(int win, int t) {
    int b   = win >> 10;
    int rem = win & 1023;
    int wh  = rem >> 5;
    int ww  = rem & 31;
    int i   = t / 7;
    int j   = t - i * 7;
    int row = (b * 224 + wh * 7 + i) * 224 + (ww * 7 + j);
    return row << 8;
}

__device__ __forceinline__ int xrow_offset(int r) {
    int w = r / 49;
    int t = r - w * 49;
    return xrow_from(w, t);
}

// ===========================================================================
// Prep kernels
// ===========================================================================
__global__ void prep_xh(const float4* __restrict__ x4) {
    int idx = blockIdx.x * 256 + threadIdx.x;
    float4 v = x4[idx];
    ((uint2*)g_xh)[idx] = make_uint2(pack_half2(v.x, v.y), pack_half2(v.z, v.w));
}

__global__ void prep_misc(const float* __restrict__ wqkv,
                          const float* __restrict__ wout,
                          const float* __restrict__ bt) {
    int blk = blockIdx.x;
    int tix = threadIdx.x;
    if (blk < 768) {
        int idx = blk * 256 + tix;
        int k = idx / 768;
        int n = idx - k * 768;
        g_wqkvTh[(size_t)n * 256 + k] = __float2half_rn(wqkv[idx]);
    } else if (blk < 1024) {
        int idx = (blk - 768) * 256 + tix;
        int k = idx >> 8;
        int n = idx & 255;
        g_woutTh[(size_t)n * 256 + k] = __float2half_rn(wout[idx]);
    } else {
        int idx = (blk - 1024) * 256 + tix;
        int h = idx >> 12;
        int r = (idx >> 6) & 63;
        int c = idx & 63;
        float v;
        if (c >= 49)      v = -1e30f;
        else if (r >= 49) v = 0.f;
        else {
            int i1 = r / 7, j1 = r - i1 * 7;
            int i2 = c / 7, j2 = c - i2 * 7;
            v = bt[((i1 - i2 + 6) * 13 + (j1 - j2 + 6)) * 8 + h];
        }
        g_biasmat[idx] = v;
    }
}

// ===========================================================================
// Fused K1+K2, PERSISTENT, packed-49, 2 HEADS per CTA:
// CTA = (5 windows, head pair). 512 thr (16 warps = 4m x 4n, warp 64x48).
// GEMM M=256 (245 real rows), N=192 (q|k|v for 2 heads), K=256, BK=64.
//
// QKV col map: n -> head hh=n/96, sec=(n%96)/32 (0=q,1=k,2=v), within=n%32.
// QKV smem row stride 400 B (200 halves).
//
// smem (bytes):
//   W     [192][264]h   @ 0       (101376)
//   Abuf  2x[256][72]h  @ 101376  (73728)   -- zeroed once
//   QKV   [256..260][200]h @ 101376 (<=104448, aliases Abuf; zeroed once)
// total 205824
// ===========================================================================
#define FUSED_SMEM 205824
#define OFF_W    0
#define OFF_AB   101376
#define OFF_QKV  101376
#define QKV_REGION 104448

__global__ __launch_bounds__(512, 1)
void qkv_attn_p(const float* __restrict__ bqkv)
{
    extern __shared__ char smem[];
    const uint32_t sbase = smem_u32(smem);

    const int tid  = threadIdx.x;
    const int wid  = tid >> 5;
    const int lane = tid & 31;
    const int cta  = blockIdx.x;
    const int hp   = cta / CPH;         // head pair 0..3
    const int i0   = cta - hp * CPH;    // first group, step CPH
    const int r0   = lane >> 2;
    const int kc   = lane & 3;
    const int lj   = lane >> 3;
    const int lq   = lane & 7;

    // ---- zero Abuf/QKV alias region ONCE ----
    {
        uint4 z = make_uint4(0, 0, 0, 0);
        uint4* p = (uint4*)(smem + OFF_AB);
        for (int i = tid; i < QKV_REGION / 16; i += 512) p[i] = z;
    }

    // ---- weight slice load ONCE: 192 rows x 256 halves (6144 ops / 512) ----
    #pragma unroll
    for (int i = 0; i < 12; i++) {
        int f   = tid + i * 512;
        int row = f >> 5;                 // n 0..191
        int q8  = (f & 31) << 3;
        int hh  = row / 96;
        int sec = (row % 96) / 32;
        int gn  = sec * 256 + (hp * 2 + hh) * 32 + (row & 31);
        CP16(sbase + OFF_W + (uint32_t)(row * 528 + q8 * 2),
             g_wqkvTh + (size_t)gn * 256 + q8);
    }
    CP_COMMIT();

    // ---- GEMM warp layout: 16 warps = 4m x 4n, warp tile 64 x 48 ----
    const int my = wid >> 2;
    const int nx = wid & 3;
    const int wm = my * 64;
    const int wn = nx * 48;

    const uint32_t a_off = (uint32_t)((wm + ((lj & 1) << 3) + lq) * 144 + ((lj >> 1) << 4));
    const uint32_t b_off = OFF_W + (uint32_t)((wn + (((lj >> 1) & 1) << 3) + lq) * 528 + ((lj & 1) << 4));

    float bias0[6], bias1[6], scl[6];
    #pragma unroll
    for (int in_ = 0; in_ < 6; in_++) {
        int col = wn + in_ * 8 + kc * 2;
        int hh  = col / 96;
        int sec = (col % 96) / 32;
        bias0[in_] = bqkv[sec * 256 + (hp * 2 + hh) * 32 + (col & 31)];
        bias1[in_] = bqkv[sec * 256 + (hp * 2 + hh) * 32 + ((col + 1) & 31)];
        scl[in_]   = (sec == 0) ? 0.5f : 1.0f;
    }

    // A-load slot geometry: 256 rows x 8 chunks = 2048 / 512 = 4 per thread
    int s_wadd[4], s_t[4], s_q8[4];
    uint32_t s_dst[4];
    #pragma unroll
    for (int i = 0; i < 4; i++) {
        int f    = tid + i * 512;
        int lrow = f >> 3;
        s_q8[i]  = (f & 7) << 3;
        s_wadd[i] = lrow / 49;
        s_t[i]    = lrow - s_wadd[i] * 49;
        s_dst[i]  = (uint32_t)(lrow * 144 + s_q8[i] * 2);
    }

    const uint32_t qkvb = sbase + OFF_QKV;

    __syncthreads();   // zero-fill visible

    for (int wg = i0; wg < NGRP; wg += CPH) {
        __syncthreads();   // prior attention reads done before Abuf overwrite

        const __half* lsrc[4];
        int lsz[4];
        #pragma unroll
        for (int i = 0; i < 4; i++) {
            int win = wg * GWIN + s_wadd[i];
            int ok  = (s_wadd[i] < GWIN) && (win < NWIN);
            lsz[i]  = ok ? 16 : 0;
            lsrc[i] = g_xh + (ok ? xrow_from(win, s_t[i]) : 0) + s_q8[i];
        }

        float acc[4][6][4];
        #pragma unroll
        for (int i = 0; i < 4; i++)
            #pragma unroll
            for (int j = 0; j < 6; j++)
                #pragma unroll
                for (int q = 0; q < 4; q++) acc[i][j][q] = 0.f;

        #pragma unroll
        for (int i = 0; i < 4; i++)
            CP16Z(sbase + OFF_AB + s_dst[i], lsrc[i], lsz[i]);
        CP_COMMIT();

        #pragma unroll
        for (int it = 0; it < 4; it++) {
            CP_WAIT(0);
            __syncthreads();
            if (it < 3) {
                uint32_t bo = OFF_AB + (uint32_t)(((it + 1) & 1) * 36864);
                int kt = (it + 1) * 64;
                #pragma unroll
                for (int i = 0; i < 4; i++)
                    CP16Z(bo + sbase + s_dst[i], lsrc[i] + kt, lsz[i]);
                CP_COMMIT();
            }

            const uint32_t abuf = sbase + OFF_AB + (uint32_t)((it & 1) * 36864);
            const uint32_t bkof = (uint32_t)(it * 128);

            #pragma unroll
            for (int k16 = 0; k16 < 64; k16 += 16) {
                uint32_t a[4][4], b2[3][4];
                #pragma unroll
                for (int im = 0; im < 4; im++)
                    ldsm_x4(a[im][0], a[im][1], a[im][2], a[im][3],
                            abuf + a_off + (uint32_t)(im * 2304 + k16 * 2));
                #pragma unroll
                for (int g = 0; g < 3; g++)
                    ldsm_x4(b2[g][0], b2[g][1], b2[g][2], b2[g][3],
                            sbase + b_off + bkof + (uint32_t)(g * 8448 + k16 * 2));
                #pragma unroll
                for (int im = 0; im < 4; im++)
                    #pragma unroll
                    for (int in_ = 0; in_ < 6; in_++)
                        mma16(acc[im][in_], a[im][0], a[im][1], a[im][2], a[im][3],
                              b2[in_ >> 1][(in_ & 1) << 1], b2[in_ >> 1][((in_ & 1) << 1) + 1]);
            }
        }
        __syncthreads();   // all Abuf reads done before QKV store aliases

        // ---- epilogue: +bias, q-scale, store fp16 into QKV rows (400B) ----
        #pragma unroll
        for (int im = 0; im < 4; im++) {
            int r_lo = wm + im * 16 + r0;
            #pragma unroll
            for (int in_ = 0; in_ < 6; in_++) {
                int colb = (wn + in_ * 8 + kc * 2) * 2;
                *(uint32_t*)(smem + OFF_QKV + r_lo * 400 + colb) =
                    pack_half2((acc[im][in_][0] + bias0[in_]) * scl[in_],
                               (acc[im][in_][1] + bias1[in_]) * scl[in_]);
                *(uint32_t*)(smem + OFF_QKV + (r_lo + 8) * 400 + colb) =
                    pack_half2((acc[im][in_][2] + bias0[in_]) * scl[in_],
                               (acc[im][in_][3] + bias1[in_]) * scl[in_]);
            }
        }
        __syncthreads();

        // ========== Phase B: attention (2 heads x 5 win x 4 quarters = 40) ==
        for (int task = wid; task < 2 * 4 * GWIN; task += 16) {
            int hh  = task / 20;
            int rem = task - hh * 20;
            int wl  = rem >> 2;
            int rq  = rem & 3;
            int win = wg * GWIN + wl;
            if (win >= NWIN) continue;
            int qrow0 = wl * 49;
            int hbyte = hh * 192;

            const uint32_t qa = (uint32_t)((qrow0 + rq * 16 + ((lj & 1) << 3) + lq) * 400 + hbyte + ((lj >> 1) << 4));
            const uint32_t kb = (uint32_t)((qrow0 + (((lj >> 1) & 1) << 3) + lq) * 400 + hbyte + 64 + ((lj & 1) << 4));
            const uint32_t vb = (uint32_t)((qrow0 + ((lj & 1) << 3) + lq) * 400 + hbyte + 128 + ((lj >> 1) << 4));
            const float* bmr0 = g_biasmat + (hp * 2 + hh) * 4096 + (rq * 16 + r0) * 64;

            float c[8][4];
            #pragma unroll
            for (int nt = 0; nt < 8; nt++)
                #pragma unroll
                for (int q = 0; q < 4; q++) c[nt][q] = 0.f;

            #pragma unroll
            for (int k16 = 0; k16 < 32; k16 += 16) {
                uint32_t a0, a1, a2, a3;
                ldsm_x4(a0, a1, a2, a3, qkvb + qa + (uint32_t)(k16 * 2));
                #pragma unroll
                for (int g = 0; g < 4; g++) {
                    uint32_t b0, b1, b2, b3;
                    ldsm_x4(b0, b1, b2, b3, qkvb + kb + (uint32_t)(g * 6400 + k16 * 2));
                    mma16(c[2 * g],     a0, a1, a2, a3, b0, b1);
                    mma16(c[2 * g + 1], a0, a1, a2, a3, b2, b3);
                }
            }

            #pragma unroll
            for (int half_ = 0; half_ < 2; half_++) {
                const float* bmr = bmr0 + half_ * 8 * 64;
                #pragma unroll
                for (int nt = 0; nt < 8; nt++) {
                    float2 bv = *(const float2*)(bmr + nt * 8 + 2 * kc);
                    c[nt][half_ * 2 + 0] += bv.x;
                    c[nt][half_ * 2 + 1] += bv.y;
                }
                float mx = -1e30f;
                #pragma unroll
                for (int nt = 0; nt < 8; nt++) {
                    mx = fmaxf(mx, c[nt][half_ * 2]);
                    mx = fmaxf(mx, c[nt][half_ * 2 + 1]);
                }
                mx = fmaxf(mx, __shfl_xor_sync(0xffffffffu, mx, 1));
                mx = fmaxf(mx, __shfl_xor_sync(0xffffffffu, mx, 2));
                float s = 0.f;
                #pragma unroll
                for (int nt = 0; nt < 8; nt++) {
                    #pragma unroll
                    for (int e = 0; e < 2; e++) {
                        float p = __expf(c[nt][half_ * 2 + e] - mx);
                        c[nt][half_ * 2 + e] = p;
                        s += p;
                    }
                }
                s += __shfl_xor_sync(0xffffffffu, s, 1);
                s += __shfl_xor_sync(0xffffffffu, s, 2);
                float inv = 1.0f / s;
                #pragma unroll
                for (int nt = 0; nt < 8; nt++) {
                    c[nt][half_ * 2 + 0] *= inv;
                    c[nt][half_ * 2 + 1] *= inv;
                }
            }

            float o[4][4];
            #pragma unroll
            for (int jn = 0; jn < 4; jn++)
                #pragma unroll
                for (int q = 0; q < 4; q++) o[jn][q] = 0.f;

            #pragma unroll
            for (int kt = 0; kt < 4; kt++) {
                uint32_t vbr[2][4];
                #pragma unroll
                for (int g = 0; g < 2; g++)
                    ldsm_x4t(vbr[g][0], vbr[g][1], vbr[g][2], vbr[g][3],
                             qkvb + vb + (uint32_t)(kt * 16 * 400 + g * 32));
                uint32_t a0 = pack_half2(c[2 * kt][0],     c[2 * kt][1]);
                uint32_t a1 = pack_half2(c[2 * kt][2],     c[2 * kt][3]);
                uint32_t a2 = pack_half2(c[2 * kt + 1][0], c[2 * kt + 1][1]);
                uint32_t a3 = pack_half2(c[2 * kt + 1][2], c[2 * kt + 1][3]);
                #pragma unroll
                for (int g = 0; g < 2; g++) {
                    mma16(o[2 * g],     a0, a1, a2, a3, vbr[g][0], vbr[g][1]);
                    mma16(o[2 * g + 1], a0, a1, a2, a3, vbr[g][2], vbr[g][3]);
                }
            }

            #pragma unroll
            for (int half_ = 0; half_ < 2; half_++) {
                int t_ = rq * 16 + r0 + half_ * 8;
                if (t_ < 49) {
                    __half* op = g_atth + ((size_t)win * 49 + t_) * 256 + (hp * 2 + hh) * 32;
                    #pragma unroll
                    for (int jn = 0; jn < 4; jn++)
                        *(uint32_t*)(op + jn * 8 + 2 * kc) =
                            pack_half2(o[jn][half_ * 2 + 0], o[jn][half_ * 2 + 1]);
                }
            }
        }
    }
}

// ===========================================================================
// K3: out = LN(g_att @ w_out + b_out + residual(fp16)), BK=64, 1-sync pipe.
// CTA 64x256, 8 warps, occ 2. (unchanged)
// ===========================================================================
#define K3_SMEM 92672
__global__ __launch_bounds__(256, 2)
void out_mma(const float* __restrict__ bout,
             const float* __restrict__ gamma,
             const float* __restrict__ beta,
             float* __restrict__ out)
{
    extern __shared__ char smem[];
    const uint32_t sbase = smem_u32(smem);
    float* s1 = (float*)(smem + 92160);
    float* s2 = (float*)(smem + 92416);

    const int tid  = threadIdx.x;
    const int wid  = tid >> 5;
    const int lane = tid & 31;
    const int m0   = blockIdx.x * 64;
    if (tid < 64) { s1[tid] = 0.f; s2[tid] = 0.f; }

    const int wm = (wid >> 2) * 32;
    const int wn = (wid & 3) * 64;
    const int r0 = lane >> 2;
    const int kc = lane & 3;
    const int lj = lane >> 3;
    const int lq = lane & 7;

    const uint32_t a_off = (uint32_t)((wm + ((lj & 1) << 3) + lq) * 144 + ((lj >> 1) << 4));
    const uint32_t b_off = 9216u + (uint32_t)((wn + (((lj >> 1) & 1) << 3) + lq) * 144 + ((lj & 1) << 4));

    float acc[2][8][4];
    #pragma unroll
    for (int i = 0; i < 2; i++)
        #pragma unroll
        for (int j = 0; j < 8; j++)
            #pragma unroll
            for (int q = 0; q < 4; q++) acc[i][j][q] = 0.f;

    #pragma unroll
    for (int i = 0; i < 2; i++) {
        int f = tid + i * 256;
        int r = f >> 3, q8 = (f & 7) << 3;
        CP16(sbase + (uint32_t)(r * 144 + q8 * 2), g_atth + (size_t)(m0 + r) * 256 + q8);
    }
    #pragma unroll
    for (int i = 0; i < 8; i++) {
        int f = tid + i * 256;
        int r = f >> 3, q8 = (f & 7) << 3;
        CP16(sbase + 9216 + (uint32_t)(r * 144 + q8 * 2), g_woutTh + (size_t)r * 256 + q8);
    }
    CP_COMMIT();

    #pragma unroll
    for (int it = 0; it < 4; it++) {
        CP_WAIT(0);
        __syncthreads();
        if (it < 3) {
            uint32_t bo = (uint32_t)(((it + 1) & 1) * 46080);
            int kt = (it + 1) * 64;
            #pragma unroll
            for (int i = 0; i < 2; i++) {
                int f = tid + i * 256;
                int r = f >> 3, q8 = (f & 7) << 3;
                CP16(sbase + bo + (uint32_t)(r * 144 + q8 * 2),
                     g_atth + (size_t)(m0 + r) * 256 + kt + q8);
            }
            #pragma unroll
            for (int i = 0; i < 8; i++) {
                int f = tid + i * 256;
                int r = f >> 3, q8 = (f & 7) << 3;
                CP16(sbase + bo + 9216 + (uint32_t)(r * 144 + q8 * 2),
                     g_woutTh + (size_t)r * 256 + kt + q8);
            }
            CP_COMMIT();
        }

        const uint32_t bufb = sbase + (uint32_t)((it & 1) * 46080);

        #pragma unroll
        for (int k16 = 0; k16 < 64; k16 += 16) {
            uint32_t a[2][4], b2[4][4];
            #pragma unroll
            for (int im = 0; im < 2; im++)
                ldsm_x4(a[im][0], a[im][1], a[im][2], a[im][3],
                        bufb + a_off + (uint32_t)(im * 2304 + k16 * 2));
            #pragma unroll
            for (int g = 0; g < 4; g++)
                ldsm_x4(b2[g][0], b2[g][1], b2[g][2], b2[g][3],
                        bufb + b_off + (uint32_t)(g * 2304 + k16 * 2));
            #pragma unroll
            for (int im = 0; im < 2; im++)
                #pragma unroll
                for (int in_ = 0; in_ < 8; in_++)
                    mma16(acc[im][in_], a[im][0], a[im][1], a[im][2], a[im][3],
                          b2[in_ >> 1][(in_ & 1) << 1], b2[in_ >> 1][((in_ & 1) << 1) + 1]);
        }
    }

    // ---- epilogue: y = acc + bias + residual(fp16 from g_xh); LN ----
    #pragma unroll
    for (int im = 0; im < 2; im++) {
        #pragma unroll
        for (int half_ = 0; half_ < 2; half_++) {
            int rl = wm + im * 16 + r0 + half_ * 8;
            const __half* xr = g_xh + xrow_offset(m0 + rl);
            float p1 = 0.f, p2 = 0.f;
            #pragma unroll
            for (int in_ = 0; in_ < 8; in_++) {
                int c = wn + in_ * 8 + kc * 2;
                float2 xv = __half22float2(*(const __half2*)(xr + c));
                float y0 = acc[im][in_][half_ * 2 + 0] + bout[c]     + xv.x;
                float y1 = acc[im][in_][half_ * 2 + 1] + bout[c + 1] + xv.y;
                acc[im][in_][half_ * 2 + 0] = y0;
                acc[im][in_][half_ * 2 + 1] = y1;
                p1 += y0 + y1;
                p2 += y0 * y0 + y1 * y1;
            }
            p1 += __shfl_xor_sync(0xffffffffu, p1, 1);
            p2 += __shfl_xor_sync(0xffffffffu, p2, 1);
            p1 += __shfl_xor_sync(0xffffffffu, p1, 2);
            p2 += __shfl_xor_sync(0xffffffffu, p2, 2);
            if (kc == 0) {
                atomicAdd(&s1[rl], p1);
                atomicAdd(&s2[rl], p2);
            }
        }
    }
    __syncthreads();

    #pragma unroll
    for (int im = 0; im < 2; im++) {
        #pragma unroll
        for (int half_ = 0; half_ < 2; half_++) {
            int rl = wm + im * 16 + r0 + half_ * 8;
            int m  = m0 + rl;
            float mean = s1[rl] * (1.0f / 256.0f);
            float var  = s2[rl] * (1.0f / 256.0f) - mean * mean;
            float rstd = rsqrtf(var + 1e-5f);
            #pragma unroll
            for (int in_ = 0; in_ < 8; in_++) {
                int c = wn + in_ * 8 + kc * 2;
                float y0 = acc[im][in_][half_ * 2 + 0];
                float y1 = acc[im][in_][half_ * 2 + 1];
                float2 o = make_float2((y0 - mean) * rstd * gamma[c]     + beta[c],
                                       (y1 - mean) * rstd * gamma[c + 1] + beta[c + 1]);
                *(float2*)(out + (size_t)m * 256 + c) = o;
            }
        }
    }
}

// ===========================================================================
extern "C" void kernel_launch(void* const* d_in, const int* in_sizes, int n_in,
                              void* d_out, int out_size)
{
    const float* x          = (const float*)d_in[0];
    const float* w_qkv      = (const float*)d_in[1];
    const float* b_qkv      = (const float*)d_in[2];
    const float* bias_table = (const float*)d_in[3];
    const float* w_out      = (const float*)d_in[4];
    const float* b_out      = (const float*)d_in[5];
    const float* ln_gamma   = (const float*)d_in[6];
    const float* ln_beta    = (const float*)d_in[7];
    float* out = (float*)d_out;

    cudaFuncSetAttribute(qkv_attn_p, cudaFuncAttributeMaxDynamicSharedMemorySize, FUSED_SMEM);
    cudaFuncSetAttribute(out_mma, cudaFuncAttributeMaxDynamicSharedMemorySize, K3_SMEM);

    prep_xh<<<50176, 256>>>((const float4*)x);
    prep_misc<<<1152, 256>>>(w_qkv, w_out, bias_table);
    qkv_attn_p<<<NPCTA, 512, FUSED_SMEM>>>(b_qkv);
    out_mma<<<MTOT / 64, 256, K3_SMEM>>>(b_out, ln_gamma, ln_beta, out);
}

// round 17
// speedup vs baseline: 1.0725x; 1.0725x over previous
#include <cuda_runtime.h>
#include <cuda_fp16.h>
#include <cstdint>

#define MTOT   200704
#define NWIN   4096
#define HEADS  8
#define GWIN   5            // windows per group (packed 49 rows each)
#define NGRP   820          // ceil(4096/5)
#define NPCTA  144          // 8 heads x 18 persistent CTAs (1/SM, 512 thr)
#define CPH    18

// Scratch (device globals; no cudaMalloc allowed)
__device__ __half g_xh   [51380224];    // x converted to fp16
__device__ __half g_atth [51380224];    // [MTOT][256] fp16
__device__ __half g_wqkvTh[768 * 256];  // w_qkv^T [N][K] fp16
__device__ __half g_woutTh[256 * 256];  // w_out^T [N][K] fp16
__device__ float  g_biasmat[8 * 64 * 64]; // per-head bias matrix, masked

// ===========================================================================
// Helpers
// ===========================================================================
__device__ __forceinline__ uint32_t smem_u32(const void* p) {
    uint32_t a;
    asm("{ .reg .u64 t; cvta.to.shared.u64 t, %1; cvt.u32.u64 %0, t; }"
        : "=r"(a) : "l"(p));
    return a;
}

__device__ __forceinline__ uint32_t pack_half2(float a, float b) {
    __half2 h = __floats2half2_rn(a, b);
    return *(uint32_t*)&h;
}

__device__ __forceinline__ void mma16(float d[4],
                                      uint32_t a0, uint32_t a1, uint32_t a2, uint32_t a3,
                                      uint32_t b0, uint32_t b1) {
    asm volatile(
        "mma.sync.aligned.m16n8k16.row.col.f32.f16.f16.f32 "
        "{%0,%1,%2,%3}, {%4,%5,%6,%7}, {%8,%9}, {%0,%1,%2,%3};"
        : "+f"(d[0]), "+f"(d[1]), "+f"(d[2]), "+f"(d[3])
        : "r"(a0), "r"(a1), "r"(a2), "r"(a3), "r"(b0), "r"(b1));
}

__device__ __forceinline__ void ldsm_x4(uint32_t& d0, uint32_t& d1,
                                        uint32_t& d2, uint32_t& d3, uint32_t addr) {
    asm volatile("ldmatrix.sync.aligned.m8n8.x4.shared.b16 {%0,%1,%2,%3}, [%4];"
                 : "=r"(d0), "=r"(d1), "=r"(d2), "=r"(d3) : "r"(addr));
}

__device__ __forceinline__ void ldsm_x4t(uint32_t& d0, uint32_t& d1,
                                         uint32_t& d2, uint32_t& d3, uint32_t addr) {
    asm volatile("ldmatrix.sync.aligned.m8n8.x4.trans.shared.b16 {%0,%1,%2,%3}, [%4];"
                 : "=r"(d0), "=r"(d1), "=r"(d2), "=r"(d3) : "r"(addr));
}

#define CP16(dst_u32, src_ptr) \
    asm volatile("cp.async.ca.shared.global [%0], [%1], 16;" \
                 :: "r"(dst_u32), "l"(src_ptr))
#define CP16Z(dst_u32, src_ptr, nbytes) \
    asm volatile("cp.async.ca.shared.global [%0], [%1], 16, %2;" \
                 :: "r"(dst_u32), "l"(src_ptr), "r"(nbytes))
#define CP_COMMIT() asm volatile("cp.async.commit_group;")
#define CP_WAIT(n)  asm volatile("cp.async.wait_group %0;" :: "n"(n))

// Pixel-row offset in x for window `win`, token `t` (t < 49)
__device__ __forceinline__ int xrow_from(int win, int t) {
    int b   = win >> 10;
    int rem = win & 1023;
    int wh  = rem >> 5;
    int ww  = rem & 31;
    int i   = t / 7;
    int j   = t - i * 7;
    int row = (b * 224 + wh * 7 + i) * 224 + (ww * 7 + j);
    return row << 8;
}

__device__ __forceinline__ int xrow_offset(int r) {
    int w = r / 49;
    int t = r - w * 49;
    return xrow_from(w, t);
}

// ===========================================================================
// Merged prep: blocks [0,50176) convert x -> fp16; [50176,50944) wqkv^T;
// [50944,51200) wout^T; [51200,51328) biasmat.
// ===========================================================================
__global__ void prep_all(const float4* __restrict__ x4,
                         const float* __restrict__ wqkv,
                         const float* __restrict__ wout,
                         const float* __restrict__ bt) {
    int blk = blockIdx.x;
    int tix = threadIdx.x;
    if (blk < 50176) {
        int idx = blk * 256 + tix;
        float4 v = x4[idx];
        ((uint2*)g_xh)[idx] = make_uint2(pack_half2(v.x, v.y), pack_half2(v.z, v.w));
    } else if (blk < 50944) {
        int idx = (blk - 50176) * 256 + tix;
        int k = idx / 768;
        int n = idx - k * 768;
        g_wqkvTh[(size_t)n * 256 + k] = __float2half_rn(wqkv[idx]);
    } else if (blk < 51200) {
        int idx = (blk - 50944) * 256 + tix;
        int k = idx >> 8;
        int n = idx & 255;
        g_woutTh[(size_t)n * 256 + k] = __float2half_rn(wout[idx]);
    } else {
        int idx = (blk - 51200) * 256 + tix;
        int h = idx >> 12;
        int r = (idx >> 6) & 63;
        int c = idx & 63;
        float v;
        if (c >= 49)      v = -1e30f;
        else if (r >= 49) v = 0.f;
        else {
            int i1 = r / 7, j1 = r - i1 * 7;
            int i2 = c / 7, j2 = c - i2 * 7;
            v = bt[((i1 - i2 + 6) * 13 + (j1 - j2 + 6)) * 8 + h];
        }
        g_biasmat[idx] = v;
    }
}

// ===========================================================================
// Fused K1+K2, PERSISTENT, packed-49 (R15 structure, best known):
// CTA = (5 windows, 1 head), 512 thr (16 warps = 8m x 2n, warp 32x48),
// 1 CTA/SM. GEMM M=256 (245 real rows), N=96, K=256, BK=64.
// ===========================================================================
#define FUSED_SMEM 124416
#define OFF_W    0
#define OFF_AB   50688
#define OFF_QKV  50688

__global__ __launch_bounds__(512, 1)
void qkv_attn_p(const float* __restrict__ bqkv)
{
    extern __shared__ char smem[];
    const uint32_t sbase = smem_u32(smem);

    const int tid  = threadIdx.x;
    const int wid  = tid >> 5;
    const int lane = tid & 31;
    const int cta  = blockIdx.x;
    const int h    = cta / CPH;
    const int i0   = cta - h * CPH;
    const int r0   = lane >> 2;
    const int kc   = lane & 3;
    const int lj   = lane >> 3;
    const int lq   = lane & 7;

    // zero Abuf/QKV alias region once (prevents uninitialized-smem NaNs)
    {
        uint4 z = make_uint4(0, 0, 0, 0);
        uint4* p = (uint4*)(smem + OFF_AB);
        for (int i = tid; i < 73728 / 16; i += 512) p[i] = z;
    }

    // weight slice load once
    #pragma unroll
    for (int i = 0; i < 6; i++) {
        int f   = tid + i * 512;
        int row = f >> 5;
        int q8  = (f & 31) << 3;
        int sec = row >> 5;
        int gn  = sec * 256 + h * 32 + (row & 31);
        CP16(sbase + OFF_W + (uint32_t)(row * 528 + q8 * 2),
             g_wqkvTh + (size_t)gn * 256 + q8);
    }
    CP_COMMIT();

    const int my = wid >> 1;
    const int nx = wid & 1;
    const int wm = my * 32;
    const int wn = nx * 48;

    const uint32_t a_off = (uint32_t)((wm + ((lj & 1) << 3) + lq) * 144 + ((lj >> 1) << 4));
    const uint32_t b_off = OFF_W + (uint32_t)((wn + (((lj >> 1) & 1) << 3) + lq) * 528 + ((lj & 1) << 4));

    float bias0[6], bias1[6], scl[6];
    #pragma unroll
    for (int in_ = 0; in_ < 6; in_++) {
        int col = wn + in_ * 8 + kc * 2;
        int sec = col >> 5;
        bias0[in_] = bqkv[sec * 256 + h * 32 + (col & 31)];
        bias1[in_] = bqkv[sec * 256 + h * 32 + ((col + 1) & 31)];
        scl[in_]   = (sec == 0) ? 0.5f : 1.0f;
    }

    int s_wadd[4], s_t[4], s_q8[4];
    uint32_t s_dst[4];
    #pragma unroll
    for (int i = 0; i < 4; i++) {
        int f    = tid + i * 512;
        int lrow = f >> 3;
        s_q8[i]  = (f & 7) << 3;
        s_wadd[i] = lrow / 49;
        s_t[i]    = lrow - s_wadd[i] * 49;
        s_dst[i]  = (uint32_t)(lrow * 144 + s_q8[i] * 2);
    }

    const uint32_t qkvb = sbase + OFF_QKV;
    const float* bmrh = g_biasmat + h * 4096 + r0 * 64;

    __syncthreads();

    for (int wg = i0; wg < NGRP; wg += CPH) {
        __syncthreads();

        const __half* lsrc[4];
        int lsz[4];
        #pragma unroll
        for (int i = 0; i < 4; i++) {
            int win = wg * GWIN + s_wadd[i];
            int ok  = (s_wadd[i] < GWIN) && (win < NWIN);
            lsz[i]  = ok ? 16 : 0;
            lsrc[i] = g_xh + (ok ? xrow_from(win, s_t[i]) : 0) + s_q8[i];
        }

        float acc[2][6][4];
        #pragma unroll
        for (int i = 0; i < 2; i++)
            #pragma unroll
            for (int j = 0; j < 6; j++)
                #pragma unroll
                for (int q = 0; q < 4; q++) acc[i][j][q] = 0.f;

        #pragma unroll
        for (int i = 0; i < 4; i++)
            CP16Z(sbase + OFF_AB + s_dst[i], lsrc[i], lsz[i]);
        CP_COMMIT();

        #pragma unroll
        for (int it = 0; it < 4; it++) {
            CP_WAIT(0);
            __syncthreads();
            if (it < 3) {
                uint32_t bo = OFF_AB + (uint32_t)(((it + 1) & 1) * 36864);
                int kt = (it + 1) * 64;
                #pragma unroll
                for (int i = 0; i < 4; i++)
                    CP16Z(bo + sbase + s_dst[i], lsrc[i] + kt, lsz[i]);
                CP_COMMIT();
            }

            const uint32_t abuf = sbase + OFF_AB + (uint32_t)((it & 1) * 36864);
            const uint32_t bkof = (uint32_t)(it * 128);

            #pragma unroll
            for (int k16 = 0; k16 < 64; k16 += 16) {
                uint32_t a[2][4], b2[3][4];
                #pragma unroll
                for (int im = 0; im < 2; im++)
                    ldsm_x4(a[im][0], a[im][1], a[im][2], a[im][3],
                            abuf + a_off + (uint32_t)(im * 2304 + k16 * 2));
                #pragma unroll
                for (int g = 0; g < 3; g++)
                    ldsm_x4(b2[g][0], b2[g][1], b2[g][2], b2[g][3],
                            sbase + b_off + bkof + (uint32_t)(g * 8448 + k16 * 2));
                #pragma unroll
                for (int im = 0; im < 2; im++)
                    #pragma unroll
                    for (int in_ = 0; in_ < 6; in_++)
                        mma16(acc[im][in_], a[im][0], a[im][1], a[im][2], a[im][3],
                              b2[in_ >> 1][(in_ & 1) << 1], b2[in_ >> 1][((in_ & 1) << 1) + 1]);
            }
        }
        __syncthreads();

        #pragma unroll
        for (int im = 0; im < 2; im++) {
            int r_lo = wm + im * 16 + r0;
            #pragma unroll
            for (int in_ = 0; in_ < 6; in_++) {
                int colb = (wn + in_ * 8 + kc * 2) * 2;
                *(uint32_t*)(smem + OFF_QKV + r_lo * 208 + colb) =
                    pack_half2((acc[im][in_][0] + bias0[in_]) * scl[in_],
                               (acc[im][in_][1] + bias1[in_]) * scl[in_]);
                *(uint32_t*)(smem + OFF_QKV + (r_lo + 8) * 208 + colb) =
                    pack_half2((acc[im][in_][2] + bias0[in_]) * scl[in_],
                               (acc[im][in_][3] + bias1[in_]) * scl[in_]);
            }
        }
        __syncthreads();

        // attention: 20 tasks over 16 warps
        for (int task = wid; task < 4 * GWIN; task += 16) {
            int wl  = task >> 2;
            int rq  = task & 3;
            int win = wg * GWIN + wl;
            if (win >= NWIN) continue;
            int qrow0 = wl * 49;

            const uint32_t qa = (uint32_t)((qrow0 + rq * 16 + ((lj & 1) << 3) + lq) * 208 + ((lj >> 1) << 4));
            const uint32_t kb = (uint32_t)((qrow0 + (((lj >> 1) & 1) << 3) + lq) * 208 + 64 + ((lj & 1) << 4));
            const uint32_t vb = (uint32_t)((qrow0 + ((lj & 1) << 3) + lq) * 208 + 128 + ((lj >> 1) << 4));
            const float* bmr0 = bmrh + rq * 1024;

            float c[8][4];
            #pragma unroll
            for (int nt = 0; nt < 8; nt++)
                #pragma unroll
                for (int q = 0; q < 4; q++) c[nt][q] = 0.f;

            #pragma unroll
            for (int k16 = 0; k16 < 32; k16 += 16) {
                uint32_t a0, a1, a2, a3;
                ldsm_x4(a0, a1, a2, a3, qkvb + qa + (uint32_t)(k16 * 2));
                #pragma unroll
                for (int g = 0; g < 4; g++) {
                    uint32_t b0, b1, b2, b3;
                    ldsm_x4(b0, b1, b2, b3, qkvb + kb + (uint32_t)(g * 3328 + k16 * 2));
                    mma16(c[2 * g],     a0, a1, a2, a3, b0, b1);
                    mma16(c[2 * g + 1], a0, a1, a2, a3, b2, b3);
                }
            }

            #pragma unroll
            for (int half_ = 0; half_ < 2; half_++) {
                const float* bmr = bmr0 + half_ * 8 * 64;
                #pragma unroll
                for (int nt = 0; nt < 8; nt++) {
                    float2 bv = *(const float2*)(bmr + nt * 8 + 2 * kc);
                    c[nt][half_ * 2 + 0] += bv.x;
                    c[nt][half_ * 2 + 1] += bv.y;
                }
                float mx = -1e30f;
                #pragma unroll
                for (int nt = 0; nt < 8; nt++) {
                    mx = fmaxf(mx, c[nt][half_ * 2]);
                    mx = fmaxf(mx, c[nt][half_ * 2 + 1]);
                }
                mx = fmaxf(mx, __shfl_xor_sync(0xffffffffu, mx, 1));
                mx = fmaxf(mx, __shfl_xor_sync(0xffffffffu, mx, 2));
                float s = 0.f;
                #pragma unroll
                for (int nt = 0; nt < 8; nt++) {
                    #pragma unroll
                    for (int e = 0; e < 2; e++) {
                        float p = __expf(c[nt][half_ * 2 + e] - mx);
                        c[nt][half_ * 2 + e] = p;
                        s += p;
                    }
                }
                s += __shfl_xor_sync(0xffffffffu, s, 1);
                s += __shfl_xor_sync(0xffffffffu, s, 2);
                float inv = 1.0f / s;
                #pragma unroll
                for (int nt = 0; nt < 8; nt++) {
                    c[nt][half_ * 2 + 0] *= inv;
                    c[nt][half_ * 2 + 1] *= inv;
                }
            }

            float o[4][4];
            #pragma unroll
            for (int jn = 0; jn < 4; jn++)
                #pragma unroll
                for (int q = 0; q < 4; q++) o[jn][q] = 0.f;

            #pragma unroll
            for (int kt = 0; kt < 4; kt++) {
                uint32_t vbr[2][4];
                #pragma unroll
                for (int g = 0; g < 2; g++)
                    ldsm_x4t(vbr[g][0], vbr[g][1], vbr[g][2], vbr[g][3],
                             qkvb + vb + (uint32_t)(kt * 16 * 208 + g * 32));
                uint32_t a0 = pack_half2(c[2 * kt][0],     c[2 * kt][1]);
                uint32_t a1 = pack_half2(c[2 * kt][2],     c[2 * kt][3]);
                uint32_t a2 = pack_half2(c[2 * kt + 1][0], c[2 * kt + 1][1]);
                uint32_t a3 = pack_half2(c[2 * kt + 1][2], c[2 * kt + 1][3]);
                #pragma unroll
                for (int g = 0; g < 2; g++) {
                    mma16(o[2 * g],     a0, a1, a2, a3, vbr[g][0], vbr[g][1]);
                    mma16(o[2 * g + 1], a0, a1, a2, a3, vbr[g][2], vbr[g][3]);
                }
            }

            #pragma unroll
            for (int half_ = 0; half_ < 2; half_++) {
                int t_ = rq * 16 + r0 + half_ * 8;
                if (t_ < 49) {
                    __half* op = g_atth + ((size_t)win * 49 + t_) * 256 + h * 32;
                    #pragma unroll
                    for (int jn = 0; jn < 4; jn++)
                        *(uint32_t*)(op + jn * 8 + 2 * kc) =
                            pack_half2(o[jn][half_ * 2 + 0], o[jn][half_ * 2 + 1]);
                }
            }
        }
    }
}

// ===========================================================================
// K3: out = LN(g_att @ w_out + b_out + residual(fp16)), BK=64, 1-sync pipe.
// CTA 64x256, 8 warps, occ 2. Residual PREFETCHED into retired buf0
// (64 rows x 264 halves, 528B stride -> conflict-free quad reads).
// ===========================================================================
#define K3_SMEM 92672
__global__ __launch_bounds__(256, 2)
void out_mma(const float* __restrict__ bout,
             const float* __restrict__ gamma,
             const float* __restrict__ beta,
             float* __restrict__ out)
{
    extern __shared__ char smem[];
    const uint32_t sbase = smem_u32(smem);
    float* s1 = (float*)(smem + 92160);
    float* s2 = (float*)(smem + 92416);

    const int tid  = threadIdx.x;
    const int wid  = tid >> 5;
    const int lane = tid & 31;
    const int m0   = blockIdx.x * 64;
    if (tid < 64) { s1[tid] = 0.f; s2[tid] = 0.f; }

    const int wm = (wid >> 2) * 32;
    const int wn = (wid & 3) * 64;
    const int r0 = lane >> 2;
    const int kc = lane & 3;
    const int lj = lane >> 3;
    const int lq = lane & 7;

    const uint32_t a_off = (uint32_t)((wm + ((lj & 1) << 3) + lq) * 144 + ((lj >> 1) << 4));
    const uint32_t b_off = 9216u + (uint32_t)((wn + (((lj >> 1) & 1) << 3) + lq) * 144 + ((lj & 1) << 4));

    float acc[2][8][4];
    #pragma unroll
    for (int i = 0; i < 2; i++)
        #pragma unroll
        for (int j = 0; j < 8; j++)
            #pragma unroll
            for (int q = 0; q < 4; q++) acc[i][j][q] = 0.f;

    #pragma unroll
    for (int i = 0; i < 2; i++) {
        int f = tid + i * 256;
        int r = f >> 3, q8 = (f & 7) << 3;
        CP16(sbase + (uint32_t)(r * 144 + q8 * 2), g_atth + (size_t)(m0 + r) * 256 + q8);
    }
    #pragma unroll
    for (int i = 0; i < 8; i++) {
        int f = tid + i * 256;
        int r = f >> 3, q8 = (f & 7) << 3;
        CP16(sbase + 9216 + (uint32_t)(r * 144 + q8 * 2), g_woutTh + (size_t)r * 256 + q8);
    }
    CP_COMMIT();

    #pragma unroll
    for (int it = 0; it < 4; it++) {
        CP_WAIT(0);
        __syncthreads();
        if (it < 3) {
            uint32_t bo = (uint32_t)(((it + 1) & 1) * 46080);
            int kt = (it + 1) * 64;
            #pragma unroll
            for (int i = 0; i < 2; i++) {
                int f = tid + i * 256;
                int r = f >> 3, q8 = (f & 7) << 3;
                CP16(sbase + bo + (uint32_t)(r * 144 + q8 * 2),
                     g_atth + (size_t)(m0 + r) * 256 + kt + q8);
            }
            #pragma unroll
            for (int i = 0; i < 8; i++) {
                int f = tid + i * 256;
                int r = f >> 3, q8 = (f & 7) << 3;
                CP16(sbase + bo + 9216 + (uint32_t)(r * 144 + q8 * 2),
                     g_woutTh + (size_t)r * 256 + kt + q8);
            }
            CP_COMMIT();
        } else {
            // last chunk computes from buf1; prefetch residual into dead buf0:
            // 64 rows x 256 halves -> smem rows of 264 halves (528 B stride)
            #pragma unroll
            for (int i = 0; i < 8; i++) {
                int f   = tid + i * 256;          // 2048 chunks of 8 halves
                int r   = f >> 5;
                int c16 = f & 31;
                CP16(sbase + (uint32_t)(r * 528 + c16 * 16),
                     g_xh + xrow_offset(m0 + r) + c16 * 8);
            }
            CP_COMMIT();
        }

        const uint32_t bufb = sbase + (uint32_t)((it & 1) * 46080);

        #pragma unroll
        for (int k16 = 0; k16 < 64; k16 += 16) {
            uint32_t a[2][4], b2[4][4];
            #pragma unroll
            for (int im = 0; im < 2; im++)
                ldsm_x4(a[im][0], a[im][1], a[im][2], a[im][3],
                        bufb + a_off + (uint32_t)(im * 2304 + k16 * 2));
            #pragma unroll
            for (int g = 0; g < 4; g++)
                ldsm_x4(b2[g][0], b2[g][1], b2[g][2], b2[g][3],
                        bufb + b_off + (uint32_t)(g * 2304 + k16 * 2));
            #pragma unroll
            for (int im = 0; im < 2; im++)
                #pragma unroll
                for (int in_ = 0; in_ < 8; in_++)
                    mma16(acc[im][in_], a[im][0], a[im][1], a[im][2], a[im][3],
                          b2[in_ >> 1][(in_ & 1) << 1], b2[in_ >> 1][((in_ & 1) << 1) + 1]);
        }
    }

    CP_WAIT(0);        // residual landed
    __syncthreads();

    // ---- epilogue: y = acc + bias + residual(smem); LN over full rows ----
    #pragma unroll
    for (int im = 0; im < 2; im++) {
        #pragma unroll
        for (int half_ = 0; half_ < 2; half_++) {
            int rl = wm + im * 16 + r0 + half_ * 8;
            const char* xr = smem + rl * 528;
            float p1 = 0.f, p2 = 0.f;
            #pragma unroll
            for (int in_ = 0; in_ < 8; in_++) {
                int c = wn + in_ * 8 + kc * 2;
                float2 xv = __half22float2(*(const __half2*)(xr + c * 2));
                float y0 = acc[im][in_][half_ * 2 + 0] + bout[c]     + xv.x;
                float y1 = acc[im][in_][half_ * 2 + 1] + bout[c + 1] + xv.y;
                acc[im][in_][half_ * 2 + 0] = y0;
                acc[im][in_][half_ * 2 + 1] = y1;
                p1 += y0 + y1;
                p2 += y0 * y0 + y1 * y1;
            }
            p1 += __shfl_xor_sync(0xffffffffu, p1, 1);
            p2 += __shfl_xor_sync(0xffffffffu, p2, 1);
            p1 += __shfl_xor_sync(0xffffffffu, p1, 2);
            p2 += __shfl_xor_sync(0xffffffffu, p2, 2);
            if (kc == 0) {
                atomicAdd(&s1[rl], p1);
                atomicAdd(&s2[rl], p2);
            }
        }
    }
    __syncthreads();

    #pragma unroll
    for (int im = 0; im < 2; im++) {
        #pragma unroll
        for (int half_ = 0; half_ < 2; half_++) {
            int rl = wm + im * 16 + r0 + half_ * 8;
            int m  = m0 + rl;
            float mean = s1[rl] * (1.0f / 256.0f);
            float var  = s2[rl] * (1.0f / 256.0f) - mean * mean;
            float rstd = rsqrtf(var + 1e-5f);
            #pragma unroll
            for (int in_ = 0; in_ < 8; in_++) {
                int c = wn + in_ * 8 + kc * 2;
                float y0 = acc[im][in_][half_ * 2 + 0];
                float y1 = acc[im][in_][half_ * 2 + 1];
                float2 o = make_float2((y0 - mean) * rstd * gamma[c]     + beta[c],
                                       (y1 - mean) * rstd * gamma[c + 1] + beta[c + 1]);
                *(float2*)(out + (size_t)m * 256 + c) = o;
            }
        }
    }
}

// ===========================================================================
extern "C" void kernel_launch(void* const* d_in, const int* in_sizes, int n_in,
                              void* d_out, int out_size)
{
    const float* x          = (const float*)d_in[0];
    const float* w_qkv      = (const float*)d_in[1];
    const float* b_qkv      = (const float*)d_in[2];
    const float* bias_table = (const float*)d_in[3];
    const float* w_out      = (const float*)d_in[4];
    const float* b_out      = (const float*)d_in[5];
    const float* ln_gamma   = (const float*)d_in[6];
    const float* ln_beta    = (const float*)d_in[7];
    float* out = (float*)d_out;

    cudaFuncSetAttribute(qkv_attn_p, cudaFuncAttributeMaxDynamicSharedMemorySize, FUSED_SMEM);
    cudaFuncSetAttribute(out_mma, cudaFuncAttributeMaxDynamicSharedMemorySize, K3_SMEM);

    prep_all<<<51328, 256>>>((const float4*)x, w_qkv, w_out, bias_table);
    qkv_attn_p<<<NPCTA, 512, FUSED_SMEM>>>(b_qkv);
    out_mma<<<MTOT / 64, 256, K3_SMEM>>>(b_out, ln_gamma, ln_beta, out);
}